// round 13
// baseline (speedup 1.0000x reference)
#include <cuda_runtime.h>
#include <cstdint>

#define VOCAB 32000
#define EMB   256
#define HID   512
#define NOUT  5
#define SEQ   512
#define BATCH 64
#define G3    1536   // 3*HID

// ---------------- scratch (static device allocations only) ----------------
__device__ float g_xg[(size_t)SEQ * BATCH * G3];   // 201 MB: precomputed input gates

// ---------------- packed fp32x2 FMA (Blackwell; 2x FFMA throughput) -------
__device__ __forceinline__ void ffma2(unsigned long long& acc,
                                      unsigned long long a,
                                      unsigned long long b) {
    asm("fma.rn.f32x2 %0, %1, %2, %0;" : "+l"(acc) : "l"(a), "l"(b));
}
__device__ __forceinline__ float hsum2(unsigned long long v) {
    float lo = __uint_as_float((unsigned)(v & 0xffffffffull));
    float hi = __uint_as_float((unsigned)(v >> 32));
    return lo + hi;
}
__device__ __forceinline__ uint32_t su32(const void* p) {
    return (uint32_t)__cvta_generic_to_shared(p);
}
__device__ __forceinline__ void mbar_wait(uint32_t addr, int parity) {
    asm volatile(
        "{\n\t.reg .pred P;\n"
        "W1_%=:\n\t"
        "mbarrier.try_wait.parity.acquire.cta.shared::cta.b64 P, [%0], %1, 0x989680;\n\t"
        "@P bra.uni W2_%=;\n\t"
        "bra.uni W1_%=;\n"
        "W2_%=:\n\t}"
        :: "r"(addr), "r"((uint32_t)parity) : "memory");
}
__device__ __forceinline__ void mbar_expect_tx(uint32_t addr, uint32_t tx) {
    asm volatile("mbarrier.arrive.expect_tx.shared.b64 _, [%0], %1;"
                 :: "r"(addr), "r"(tx) : "memory");
}
__device__ __forceinline__ void mbar_arrive_rank(uint32_t addr, uint32_t rank) {
    asm volatile(
        "{\n\t.reg .b32 ra;\n\t"
        "mapa.shared::cluster.u32 ra, %0, %1;\n\t"
        "mbarrier.arrive.shared::cluster.b64 _, [ra];\n\t}"
        :: "r"(addr), "r"(rank) : "memory");
}
__device__ __forceinline__ void bulk_s2s(uint32_t dst_local, uint32_t src_local,
                                         uint32_t bar_local, uint32_t rank,
                                         uint32_t bytes) {
    asm volatile(
        "{\n\t.reg .b32 rd, rb;\n\t"
        "mapa.shared::cluster.u32 rd, %0, %3;\n\t"
        "mapa.shared::cluster.u32 rb, %2, %3;\n\t"
        "cp.async.bulk.shared::cluster.shared::cta.mbarrier::complete_tx::bytes "
        "[rd], [%1], %4, [rb];\n\t}"
        :: "r"(dst_local), "r"(src_local), "r"(bar_local), "r"(rank), "r"(bytes)
        : "memory");
}

// ---------------- phase 1: x_gates = emb[seq] @ w_ih^T + b_ih -------------
// grid (64 batch, 8 s-tiles of 64, 12 n-chunks of 128), 256 threads.
#define P1_SMEM ((64 * 260 + 128 * 258) * 4)
__global__ void __launch_bounds__(256, 1)
k_xgates(const int* __restrict__ seq, const int* __restrict__ lengths,
         const float* __restrict__ emb, const float* __restrict__ w_ih,
         const float* __restrict__ b_ih) {
    const int b = blockIdx.x, st = blockIdx.y, nc = blockIdx.z;
    const int s0 = st * 64, n0 = nc * 128;
    const int tid = threadIdx.x;
    if (s0 >= lengths[b]) return;  // dead steps never read downstream

    extern __shared__ float sm1[];
    float* xs = sm1;               // [64][260]
    float* ws = sm1 + 64 * 260;    // [128][258] = [kp][129 float2]

    {
        int r = tid >> 2, part = tid & 3;
        int tok = seq[(s0 + r) * BATCH + b];
        const float4* src = reinterpret_cast<const float4*>(emb) +
                            (size_t)tok * (EMB / 4) + part * 16;
        float* drow = xs + r * 260;
#pragma unroll
        for (int i = 0; i < 16; ++i) {
            float4 v = src[i];
            int k = (part * 16 + i) * 4;
            drow[k] = v.x; drow[k + 1] = v.y; drow[k + 2] = v.z; drow[k + 3] = v.w;
        }
    }
    {
        int n = tid >> 1, half = tid & 1;
        const float4* src = reinterpret_cast<const float4*>(
            w_ih + (size_t)(n0 + n) * EMB + half * 128);
#pragma unroll
        for (int i = 0; i < 32; ++i) {
            float4 v = src[i];
            int kp = half * 64 + i * 2;
            float* d0 = ws + (kp * 129 + n) * 2;
            d0[0] = v.x; d0[1] = v.y;
            float* d1 = ws + ((kp + 1) * 129 + n) * 2;
            d1[0] = v.z; d1[1] = v.w;
        }
    }
    __syncthreads();

    const int tn = tid & 15, ts = tid >> 4;
    unsigned long long acc[4][8];
#pragma unroll
    for (int i = 0; i < 4; ++i)
#pragma unroll
        for (int j = 0; j < 8; ++j) acc[i][j] = 0ull;

    const float* xbase = xs + ts * 260;
#pragma unroll 2
    for (int kp = 0; kp < 128; ++kp) {
        unsigned long long a[4], w[8];
#pragma unroll
        for (int i = 0; i < 4; ++i)
            a[i] = *reinterpret_cast<const unsigned long long*>(xbase + i * 16 * 260 + 2 * kp);
#pragma unroll
        for (int j = 0; j < 8; ++j)
            w[j] = *reinterpret_cast<const unsigned long long*>(ws + (kp * 129 + j * 16 + tn) * 2);
#pragma unroll
        for (int i = 0; i < 4; ++i)
#pragma unroll
            for (int j = 0; j < 8; ++j) ffma2(acc[i][j], a[i], w[j]);
    }
#pragma unroll
    for (int i = 0; i < 4; ++i) {
        int s = s0 + ts + i * 16;
        float* orow = g_xg + ((size_t)s * BATCH + b) * G3 + n0;
#pragma unroll
        for (int j = 0; j < 8; ++j) {
            int n = j * 16 + tn;
            orow[n] = hsum2(acc[i][j]) + b_ih[n0 + n];
        }
    }
}

// ---------------- phase 2: persistent GRU, DSMEM one-sided exchange -------
// grid (16 slices, 8 groups); each group = one 16-CTA cluster (rank = kg).
// group g owns batches {g, g+8, ..., g+56} (lengths DESC in local bl).
// h lives only in SMEM: arrival buffer hsm[16 kg][8 bl][32] filled by peers'
// cp.async.bulk (tx-counted on local 'full' mbarrier); GEMM reads it in
// place. 'empty' mbarrier (count 16) grants producers overwrite permission.
// No global barrier, no fences on the critical path.
#define P2_SMEM ((128 * 96 * 4 + 16 * 256 + 2 * 256 + 4 * 8 * 96) * 4)

template <int NB>
__device__ __forceinline__ void gemm_q2(const ulonglong2* __restrict__ wp,
                                        const ulonglong2* __restrict__ hp,
                                        float* __restrict__ vA,
                                        float* __restrict__ vB) {
    unsigned long long aL[NB], aH[NB], bL[NB], bH[NB];
#pragma unroll
    for (int b = 0; b < NB; ++b) { aL[b] = 0; aH[b] = 0; bL[b] = 0; bH[b] = 0; }
#pragma unroll
    for (int seg = 0; seg < 2; ++seg) {
#pragma unroll 4
        for (int i = 0; i < 8; ++i) {
            ulonglong2 wA = wp[(seg * 8 + i) * 96];
            ulonglong2 wB = wp[(seg * 8 + i) * 96 + 48];
#pragma unroll
            for (int b = 0; b < NB; ++b) {
                ulonglong2 h = hp[seg * 64 + b * 8 + i];
                ffma2(aL[b], wA.x, h.x); ffma2(aH[b], wA.y, h.y);
                ffma2(bL[b], wB.x, h.x); ffma2(bH[b], wB.y, h.y);
            }
        }
    }
#pragma unroll
    for (int b = 0; b < NB; ++b) {
        vA[b] = hsum2(aL[b]) + hsum2(aH[b]);
        vB[b] = hsum2(bL[b]) + hsum2(bH[b]);
    }
}

__global__ void __launch_bounds__(384, 1) __cluster_dims__(16, 1, 1)
k_gru(const float* __restrict__ w_hh, const float* __restrict__ b_hh,
      const int* __restrict__ lengths, const float* __restrict__ w_out,
      const float* __restrict__ b_out, float* __restrict__ out) {
    const int kg = blockIdx.x;   // 0..15 hidden slice = cluster rank
    const int g  = blockIdx.y;   // 0..7  batch group  = cluster id
    const int j0 = kg * 32;

    extern __shared__ float sm2[];
    float4* w4  = reinterpret_cast<float4*>(sm2);   // [128 kp2][96 q] 192KB
    float*  hsm = sm2 + 128 * 96 * 4;               // [16 kg][8 bl][32] 16KB
    float*  stg = hsm + 16 * 256;                   // [2][8 bl][32]     2KB
    float*  hgp = stg + 2 * 256;                    // [4 kqm][8 bl][96] 12KB
    __shared__ int   len_loc[8];
    __shared__ float lg[8][NOUT];
    __shared__ alignas(8) unsigned long long mbar[2];  // [0]=full [1]=empty

    const int tid = threadIdx.x;
    const int kq8 = tid / 48;           // 0..7 K-eighth
    const int qh  = tid % 48;           // rows qh, qh+48
    const int kqm = kq8 & 3;
    const bool lo = (kq8 < 4);

    const uint32_t full_a  = su32(&mbar[0]);
    const uint32_t empty_a = su32(&mbar[1]);
    const uint32_t hsm_a   = su32(hsm);
    const uint32_t stg_a   = su32(stg);

    if (tid < 8) len_loc[tid] = lengths[g + 8 * tid];
    if (tid == 0) {
        asm volatile("mbarrier.init.shared.b64 [%0], %1;" :: "r"(full_a),  "r"(1)  : "memory");
        asm volatile("mbarrier.init.shared.b64 [%0], %1;" :: "r"(empty_a), "r"(16) : "memory");
        asm volatile("fence.mbarrier_init.release.cluster;" ::: "memory");
    }

    // persistent weight slice (once): w4[kp2*96+q] = w_hh[row(q)][4kp2..]
    for (int idx = tid; idx < 96 * 128; idx += 384) {
        int qq = idx >> 7, kp2 = idx & 127;
        int row = (qq / 32) * HID + j0 + (qq % 32);
        w4[kp2 * 96 + qq] =
            *(reinterpret_cast<const float4*>(w_hh + (size_t)row * HID) + kp2);
    }
    __syncthreads();
    asm volatile("barrier.cluster.arrive.aligned;" ::: "memory");
    asm volatile("barrier.cluster.wait.aligned;" ::: "memory");

    const int nsteps = len_loc[0];      // lengths descending in bl

    // ---- pointwise thread state (tid < 256 handles one (bl, jl)) ----
    const bool pw = (tid < 256);
    const int bl = tid >> 5, jl = tid & 31;
    const int bg = g + 8 * bl;
    int mylen = 0;
    float bhr = 0.f, bhz = 0.f, bhn = 0.f;
    const float* xp = nullptr;
    float hcur = 0.f;
    if (pw) {
        mylen = len_loc[bl];
        bhr = b_hh[j0 + jl];
        bhz = b_hh[HID + j0 + jl];
        bhn = b_hh[2 * HID + j0 + jl];
        xp  = g_xg + (size_t)bg * G3 + j0 + jl;
    }

    const ulonglong2* wbase =
        reinterpret_cast<const ulonglong2*>(w4) + (size_t)(kq8 * 16) * 96 + qh;
    const ulonglong2* hbase =
        reinterpret_cast<const ulonglong2*>(hsm) + kq8 * 128;
    float* oA = hgp + kqm * 768 + qh;   // +b*96
    float* oB = oA + 48;

    for (int t = 0; t < nsteps; ++t) {
        // prefetch this step's xg (DRAM) -- in flight through wait + GEMM
        float x0 = 0.f, x1 = 0.f, x2 = 0.f;
        const bool act = pw && (t < mylen);
        if (act) {
            x0 = __ldcs(xp);
            x1 = __ldcs(xp + HID);
            x2 = __ldcs(xp + 2 * HID);
            xp += (size_t)BATCH * G3;
        }

        if (t > 0) {
            mbar_wait(full_a, (t - 1) & 1);   // h(t) fully arrived (acquire)

            int A = 0;
#pragma unroll
            for (int i = 0; i < 8; ++i) A += (t < len_loc[i]) ? 1 : 0;

            float vA[8], vB[8];
            int NB;
            if (A > 6)      { gemm_q2<8>(wbase, hbase, vA, vB); NB = 8; }
            else if (A > 4) { gemm_q2<6>(wbase, hbase, vA, vB); NB = 6; }
            else if (A > 2) { gemm_q2<4>(wbase, hbase, vA, vB); NB = 4; }
            else            { gemm_q2<2>(wbase, hbase, vA, vB); NB = 2; }

            if (lo) {
#pragma unroll 4
                for (int b = 0; b < NB; ++b) { oA[b * 96] = vA[b]; oB[b * 96] = vB[b]; }
            }
            __syncthreads();               // all GEMM reads of hsm are done
            if (tid == 0) {                // grant overwrite permission
#pragma unroll 1
                for (uint32_t p = 0; p < 16; ++p) mbar_arrive_rank(empty_a, p);
            }
            if (!lo) {
#pragma unroll 4
                for (int b = 0; b < NB; ++b) { oA[b * 96] += vA[b]; oB[b * 96] += vB[b]; }
            }
            __syncthreads();
        }

        // ---- pointwise GRU update (h element lives in hcur register) ----
        if (pw) {
            if (act) {
                float sr = 0.f, sz = 0.f, sn = 0.f;
                if (t > 0) {
                    const float* hgb = hgp + bl * 96 + jl;
                    sr = hgb[0]  + hgb[768]      + hgb[1536]      + hgb[2304];
                    sz = hgb[32] + hgb[768 + 32] + hgb[1536 + 32] + hgb[2304 + 32];
                    sn = hgb[64] + hgb[768 + 64] + hgb[1536 + 64] + hgb[2304 + 64];
                }
                float gr  = sr + bhr + x0;
                float gz  = sz + bhz + x1;
                float gnh = sn + bhn;
                float r = 1.0f / (1.0f + __expf(-gr));
                float z = 1.0f / (1.0f + __expf(-gz));
                float n = tanhf(x2 + r * gnh);
                hcur = (1.0f - z) * n + z * hcur;
            }
            stg[(t & 1) * 256 + bl * 32 + jl] = hcur;  // always (frozen keep last)
        }
        __syncthreads();   // stg complete; hgp reads complete

        // ---- one-sided exchange of h(t+1) (skip after last useful step) --
        if (t <= nsteps - 2 && tid == 0) {
            asm volatile("fence.proxy.async.shared::cta;" ::: "memory");
            if (t >= 1) mbar_wait(empty_a, (t - 1) & 1);  // buffer free everywhere
            int An = 0;
#pragma unroll
            for (int i = 0; i < 8; ++i) An += (t + 1 < len_loc[i]) ? 1 : 0;
            uint32_t bytes = (uint32_t)An * 128u;
            mbar_expect_tx(full_a, 16u * bytes);
            uint32_t src = stg_a + (t & 1) * 1024u;
            uint32_t dst = hsm_a + kg * 1024u;
#pragma unroll 1
            for (uint32_t p = 0; p < 16; ++p)
                bulk_s2s(dst, src, full_a, p, bytes);
        }
    }

    // ---- final: ship full h block to rank 0 for the output head ----------
    if (tid == 0) {
        asm volatile("fence.proxy.async.shared::cta;" ::: "memory");
        if (nsteps >= 2) mbar_wait(empty_a, (nsteps - 2) & 1);
        if (kg == 0) mbar_expect_tx(full_a, 16u * 1024u);
        bulk_s2s(hsm_a + kg * 1024u, stg_a + ((nsteps - 1) & 1) * 1024u,
                 full_a, 0, 1024u);
    }

    if (kg == 0) {
        mbar_wait(full_a, (nsteps - 1) & 1);   // all 16 final blocks in hsm
        const int wid = tid >> 5, lane = tid & 31;
        for (int p = wid; p < 8 * NOUT; p += 12) {
            int bb = p / NOUT, oo = p % NOUT;
            float s = 0.f;
#pragma unroll
            for (int i = 0; i < 16; ++i)
                s += hsm[i * 256 + bb * 32 + lane] * w_out[oo * HID + i * 32 + lane];
#pragma unroll
            for (int d = 16; d; d >>= 1) s += __shfl_down_sync(0xffffffffu, s, d);
            if (lane == 0) lg[bb][oo] = s + b_out[oo];
        }
        __syncthreads();
        if (tid < 8) {
            float m = lg[tid][0];
#pragma unroll
            for (int i = 1; i < NOUT; ++i) m = fmaxf(m, lg[tid][i]);
            float sum = 0.f;
#pragma unroll
            for (int i = 0; i < NOUT; ++i) sum += __expf(lg[tid][i] - m);
            float lse = m + logf(sum);
#pragma unroll
            for (int i = 0; i < NOUT; ++i)
                out[(g + 8 * tid) * NOUT + i] = lg[tid][i] - lse;
        }
    }

    // keep cluster alive until rank 0 consumed all final copies
    asm volatile("barrier.cluster.arrive.aligned;" ::: "memory");
    asm volatile("barrier.cluster.wait.aligned;" ::: "memory");
}

// ---------------- launch ---------------------------------------------------
extern "C" void kernel_launch(void* const* d_in, const int* in_sizes, int n_in,
                              void* d_out, int out_size) {
    const int*   seq     = (const int*)d_in[0];
    const int*   lengths = (const int*)d_in[1];
    const float* emb     = (const float*)d_in[2];
    const float* w_ih    = (const float*)d_in[3];
    const float* w_hh    = (const float*)d_in[4];
    const float* b_ih    = (const float*)d_in[5];
    const float* b_hh    = (const float*)d_in[6];
    const float* w_out   = (const float*)d_in[7];
    const float* b_out   = (const float*)d_in[8];
    float*       out     = (float*)d_out;

    cudaFuncSetAttribute(k_xgates, cudaFuncAttributeMaxDynamicSharedMemorySize, P1_SMEM);
    cudaFuncSetAttribute(k_gru,    cudaFuncAttributeMaxDynamicSharedMemorySize, P2_SMEM);
    cudaFuncSetAttribute(k_gru,    cudaFuncAttributeNonPortableClusterSizeAllowed, 1);

    k_xgates<<<dim3(BATCH, SEQ / 64, G3 / 128), 256, P1_SMEM>>>(seq, lengths, emb, w_ih, b_ih);
    k_gru<<<dim3(16, 8), 384, P2_SMEM>>>(w_hh, b_hh, lengths, w_out, b_out, out);
}

// round 14
// speedup vs baseline: 1.1360x; 1.1360x over previous
#include <cuda_runtime.h>
#include <cstdint>

#define VOCAB 32000
#define EMB   256
#define HID   512
#define NOUT  5
#define SEQ   512
#define BATCH 64
#define G3    1536   // 3*HID

// ---------------- scratch (static device allocations only) ----------------
__device__ float g_xg[(size_t)SEQ * BATCH * G3];   // 201 MB: precomputed input gates
__device__ float g_h[2][BATCH * HID];              // double-buffered hidden state
__device__ float g_hfinal[BATCH * HID];            // final hidden per batch

// ---------------- packed fp32x2 FMA (Blackwell; 2x FFMA throughput) -------
__device__ __forceinline__ void ffma2(unsigned long long& acc,
                                      unsigned long long a,
                                      unsigned long long b) {
    asm("fma.rn.f32x2 %0, %1, %2, %0;" : "+l"(acc) : "l"(a), "l"(b));
}
__device__ __forceinline__ float hsum2(unsigned long long v) {
    float lo = __uint_as_float((unsigned)(v & 0xffffffffull));
    float hi = __uint_as_float((unsigned)(v >> 32));
    return lo + hi;
}
__device__ __forceinline__ uint32_t su32(const void* p) {
    return (uint32_t)__cvta_generic_to_shared(p);
}
// acquire at CLUSTER scope: pairs with peers' release-arrives
__device__ __forceinline__ void mbar_wait(uint32_t addr, uint32_t parity) {
    asm volatile(
        "{\n\t.reg .pred P;\n"
        "W1_%=:\n\t"
        "mbarrier.try_wait.parity.acquire.cluster.shared::cta.b64 P, [%0], %1, 0x989680;\n\t"
        "@P bra.uni W2_%=;\n\t"
        "bra.uni W1_%=;\n"
        "W2_%=:\n\t}"
        :: "r"(addr), "r"(parity) : "memory");
}
// single remote arrive on cluster rank's copy of a local-offset mbarrier
__device__ __forceinline__ void mbar_arrive_rank(uint32_t addr, uint32_t rank) {
    asm volatile(
        "{\n\t.reg .b32 ra;\n\t"
        "mapa.shared::cluster.u32 ra, %0, %1;\n\t"
        "mbarrier.arrive.release.cluster.shared::cluster.b64 _, [ra];\n\t}"
        :: "r"(addr), "r"(rank) : "memory");
}

// ---------------- phase 1: x_gates = emb[seq] @ w_ih^T + b_ih -------------
// grid (64 batch, 8 s-tiles of 64, 12 n-chunks of 128), 256 threads.
#define P1_SMEM ((64 * 260 + 128 * 258) * 4)
__global__ void __launch_bounds__(256, 1)
k_xgates(const int* __restrict__ seq, const int* __restrict__ lengths,
         const float* __restrict__ emb, const float* __restrict__ w_ih,
         const float* __restrict__ b_ih) {
    const int b = blockIdx.x, st = blockIdx.y, nc = blockIdx.z;
    const int s0 = st * 64, n0 = nc * 128;
    const int tid = threadIdx.x;
    if (s0 >= lengths[b]) return;  // dead steps never read downstream

    extern __shared__ float sm1[];
    float* xs = sm1;               // [64][260]
    float* ws = sm1 + 64 * 260;    // [128][258] = [kp][129 float2]

    {
        int r = tid >> 2, part = tid & 3;
        int tok = seq[(s0 + r) * BATCH + b];
        const float4* src = reinterpret_cast<const float4*>(emb) +
                            (size_t)tok * (EMB / 4) + part * 16;
        float* drow = xs + r * 260;
#pragma unroll
        for (int i = 0; i < 16; ++i) {
            float4 v = src[i];
            int k = (part * 16 + i) * 4;
            drow[k] = v.x; drow[k + 1] = v.y; drow[k + 2] = v.z; drow[k + 3] = v.w;
        }
    }
    {
        int n = tid >> 1, half = tid & 1;
        const float4* src = reinterpret_cast<const float4*>(
            w_ih + (size_t)(n0 + n) * EMB + half * 128);
#pragma unroll
        for (int i = 0; i < 32; ++i) {
            float4 v = src[i];
            int kp = half * 64 + i * 2;
            float* d0 = ws + (kp * 129 + n) * 2;
            d0[0] = v.x; d0[1] = v.y;
            float* d1 = ws + ((kp + 1) * 129 + n) * 2;
            d1[0] = v.z; d1[1] = v.w;
        }
    }
    __syncthreads();

    const int tn = tid & 15, ts = tid >> 4;
    unsigned long long acc[4][8];
#pragma unroll
    for (int i = 0; i < 4; ++i)
#pragma unroll
        for (int j = 0; j < 8; ++j) acc[i][j] = 0ull;

    const float* xbase = xs + ts * 260;
#pragma unroll 2
    for (int kp = 0; kp < 128; ++kp) {
        unsigned long long a[4], w[8];
#pragma unroll
        for (int i = 0; i < 4; ++i)
            a[i] = *reinterpret_cast<const unsigned long long*>(xbase + i * 16 * 260 + 2 * kp);
#pragma unroll
        for (int j = 0; j < 8; ++j)
            w[j] = *reinterpret_cast<const unsigned long long*>(ws + (kp * 129 + j * 16 + tn) * 2);
#pragma unroll
        for (int i = 0; i < 4; ++i)
#pragma unroll
            for (int j = 0; j < 8; ++j) ffma2(acc[i][j], a[i], w[j]);
    }
#pragma unroll
    for (int i = 0; i < 4; ++i) {
        int s = s0 + ts + i * 16;
        float* orow = g_xg + ((size_t)s * BATCH + b) * G3 + n0;
#pragma unroll
        for (int j = 0; j < 8; ++j) {
            int n = j * 16 + tn;
            orow[n] = hsum2(acc[i][j]) + b_ih[n0 + n];
        }
    }
}

// ---------------- phase 2: persistent GRU recurrence + fused output -------
// grid (16 slices, 8 groups); each group = one 16-CTA cluster (rank = kg).
// group g owns batches {g, g+8, ..., g+56} (lengths DESC in local bl).
// Weights persistent in SMEM [kp2][96 q] float4 (192 KB); h exchanged via
// L2 (STG / __ldcg). Step sync: per-CTA mbar[2] (count 16, ping-pong by
// round); end of round r, threads 0-15 each send ONE remote
// arrive.release.cluster to rank tid's mbar[r&1]; consumers try_wait
// (acquire.cluster, HW sleep). No fences/atomics/polling on the path.
#define P2_SMEM ((128 * 96 * 4 + 8 * 512 + 4 * 8 * 96) * 4)

template <int NB>
__device__ __forceinline__ void gemm_q2(const ulonglong2* __restrict__ wp,
                                        const ulonglong2* __restrict__ hp,
                                        float* __restrict__ vA,
                                        float* __restrict__ vB) {
    unsigned long long aL[NB], aH[NB], bL[NB], bH[NB];
#pragma unroll
    for (int b = 0; b < NB; ++b) { aL[b] = 0; aH[b] = 0; bL[b] = 0; bH[b] = 0; }
#pragma unroll 4
    for (int i = 0; i < 16; ++i) {
        ulonglong2 wA = wp[i * 96];
        ulonglong2 wB = wp[i * 96 + 48];
#pragma unroll
        for (int b = 0; b < NB; ++b) {
            ulonglong2 h = hp[b * 128 + i];
            ffma2(aL[b], wA.x, h.x); ffma2(aH[b], wA.y, h.y);
            ffma2(bL[b], wB.x, h.x); ffma2(bH[b], wB.y, h.y);
        }
    }
#pragma unroll
    for (int b = 0; b < NB; ++b) {
        vA[b] = hsum2(aL[b]) + hsum2(aH[b]);
        vB[b] = hsum2(bL[b]) + hsum2(bH[b]);
    }
}

__global__ void __launch_bounds__(384, 1) __cluster_dims__(16, 1, 1)
k_gru(const float* __restrict__ w_hh, const float* __restrict__ b_hh,
      const int* __restrict__ lengths, const float* __restrict__ w_out,
      const float* __restrict__ b_out, float* __restrict__ out) {
    const int kg = blockIdx.x;   // 0..15 hidden slice = cluster rank
    const int g  = blockIdx.y;   // 0..7  batch group  = cluster id
    const int j0 = kg * 32;

    extern __shared__ float sm2[];
    float4* w4  = reinterpret_cast<float4*>(sm2);   // [128 kp2][96 q] 192KB
    float*  hsm = sm2 + 128 * 96 * 4;               // [8 bl][512]      16KB
    float*  hgp = hsm + 8 * 512;                    // [4 kqm][8 bl][96]12KB
    __shared__ int   len_loc[8];
    __shared__ float lg[8][NOUT];
    __shared__ alignas(8) unsigned long long mbar[2];  // round ping-pong

    const int tid = threadIdx.x;
    const int kq8 = tid / 48;           // 0..7 K-eighth
    const int qh  = tid % 48;           // rows qh, qh+48
    const int kqm = kq8 & 3;
    const bool lo = (kq8 < 4);

    const uint32_t mb0 = su32(&mbar[0]);
    const uint32_t mb1 = su32(&mbar[1]);

    if (tid < 8) len_loc[tid] = lengths[g + 8 * tid];
    if (tid == 0) {
        asm volatile("mbarrier.init.shared.b64 [%0], %1;" :: "r"(mb0), "r"(16) : "memory");
        asm volatile("mbarrier.init.shared.b64 [%0], %1;" :: "r"(mb1), "r"(16) : "memory");
        asm volatile("fence.mbarrier_init.release.cluster;" ::: "memory");
    }

    // persistent weight slice (once): w4[kp2*96+q] = w_hh[row(q)][4kp2..]
    for (int idx = tid; idx < 96 * 128; idx += 384) {
        int qq = idx >> 7, kp2 = idx & 127;
        int row = (qq / 32) * HID + j0 + (qq % 32);
        w4[kp2 * 96 + qq] =
            *(reinterpret_cast<const float4*>(w_hh + (size_t)row * HID) + kp2);
    }
    __syncthreads();
    asm volatile("barrier.cluster.arrive.aligned;" ::: "memory");   // inits visible
    asm volatile("barrier.cluster.wait.aligned;" ::: "memory");

    const int nsteps = len_loc[0];      // lengths descending in bl

    // ---- pointwise thread state (tid < 256 handles one (bl, jl)) ----
    const bool pw = (tid < 256);
    const int bl = tid >> 5, jl = tid & 31;
    const int bg = g + 8 * bl;
    int mylen = 0;
    float bhr = 0.f, bhz = 0.f, bhn = 0.f;
    const float* xp = nullptr;
    size_t hoff = 0;
    float hcur = 0.f;
    if (pw) {
        mylen = len_loc[bl];
        bhr = b_hh[j0 + jl];
        bhz = b_hh[HID + j0 + jl];
        bhn = b_hh[2 * HID + j0 + jl];
        xp  = g_xg + (size_t)bg * G3 + j0 + jl;
        hoff = (size_t)bg * HID + j0 + jl;
    }

    const ulonglong2* wbase =
        reinterpret_cast<const ulonglong2*>(w4) + (size_t)(kq8 * 16) * 96 + qh;
    const ulonglong2* hbase =
        reinterpret_cast<const ulonglong2*>(hsm) + kq8 * 16;
    float* oA = hgp + kqm * 768 + qh;   // +b*96
    float* oB = oA + 48;

    for (int t = 0; t < nsteps; ++t) {
        float* hw = g_h[(t + 1) & 1];

        // prefetch this step's xg (DRAM) -- in flight through wait + GEMM
        float x0 = 0.f, x1 = 0.f, x2 = 0.f;
        const bool act = pw && (t < mylen);
        if (act) {
            x0 = __ldcs(xp);
            x1 = __ldcs(xp + HID);
            x2 = __ldcs(xp + 2 * HID);
            xp += (size_t)BATCH * G3;
        }

        if (t > 0) {
            // wait for round t-1 (all peers stored h(t)) — HW-sleep, acquire
            const int r = t - 1;
            mbar_wait((r & 1) ? mb1 : mb0, (uint32_t)((r >> 1) & 1));

            const float* hr = g_h[t & 1];
            int A = 0;
#pragma unroll
            for (int i = 0; i < 8; ++i) A += (t < len_loc[i]) ? 1 : 0;

            // stage active h through L2
            for (int idx = tid; idx < A * 128; idx += 384) {
                int bb = idx >> 7, k4 = idx & 127;
                float4 v = __ldcg(
                    reinterpret_cast<const float4*>(hr) + (size_t)(g + 8 * bb) * 128 + k4);
                reinterpret_cast<float4*>(hsm)[bb * 128 + k4] = v;
            }
            __syncthreads();

            // GEMM over this K-eighth, rows {qh, qh+48}, NB batches
            float vA[8], vB[8];
            int NB;
            if (A > 6)      { gemm_q2<8>(wbase, hbase, vA, vB); NB = 8; }
            else if (A > 4) { gemm_q2<6>(wbase, hbase, vA, vB); NB = 6; }
            else if (A > 2) { gemm_q2<4>(wbase, hbase, vA, vB); NB = 4; }
            else            { gemm_q2<2>(wbase, hbase, vA, vB); NB = 2; }

            // fold 8 K-partials to 4: lo writes, hi adds
            if (lo) {
#pragma unroll 4
                for (int b = 0; b < NB; ++b) { oA[b * 96] = vA[b]; oB[b * 96] = vB[b]; }
            }
            __syncthreads();
            if (!lo) {
#pragma unroll 4
                for (int b = 0; b < NB; ++b) { oA[b * 96] += vA[b]; oB[b * 96] += vB[b]; }
            }
            __syncthreads();
        }

        // ---- pointwise GRU update (h element lives in hcur register) ----
        if (act) {
            float sr = 0.f, sz = 0.f, sn = 0.f;
            if (t > 0) {
                const float* hgb = hgp + bl * 96 + jl;
                sr = hgb[0]  + hgb[768]      + hgb[1536]      + hgb[2304];
                sz = hgb[32] + hgb[768 + 32] + hgb[1536 + 32] + hgb[2304 + 32];
                sn = hgb[64] + hgb[768 + 64] + hgb[1536 + 64] + hgb[2304 + 64];
            }
            float gr  = sr + bhr + x0;
            float gz  = sz + bhz + x1;
            float gnh = sn + bhn;
            float r = 1.0f / (1.0f + __expf(-gr));
            float z = 1.0f / (1.0f + __expf(-gz));
            float n = tanhf(x2 + r * gnh);
            hcur = (1.0f - z) * n + z * hcur;
            hw[hoff] = hcur;
        }

        // ---- end of round t: 16 parallel one-shot remote arrives ----
        __syncthreads();                     // h stores issued by all threads
        if (tid < 16)
            mbar_arrive_rank((t & 1) ? mb1 : mb0, (uint32_t)tid);
    }

    // ---- final round: publish h, arrive once more, rank 0 reduces --------
    if (pw) g_hfinal[hoff] = hcur;
    __syncthreads();
    if (tid < 16)
        mbar_arrive_rank((nsteps & 1) ? mb1 : mb0, (uint32_t)tid);

    if (kg == 0) {
        mbar_wait((nsteps & 1) ? mb1 : mb0, (uint32_t)((nsteps >> 1) & 1));
        const int wid = tid >> 5, lane = tid & 31;
        for (int p = wid; p < 8 * NOUT; p += 12) {
            int bb = p / NOUT, oo = p % NOUT;
            const float4* h4 =
                reinterpret_cast<const float4*>(g_hfinal + (size_t)(g + 8 * bb) * HID);
            const float4* w4o =
                reinterpret_cast<const float4*>(w_out + (size_t)oo * HID);
            float s = 0.f;
#pragma unroll
            for (int i = 0; i < 4; ++i) {
                float4 hv = __ldcg(h4 + lane + 32 * i);
                float4 wv = w4o[lane + 32 * i];
                s += hv.x * wv.x + hv.y * wv.y + hv.z * wv.z + hv.w * wv.w;
            }
#pragma unroll
            for (int d = 16; d; d >>= 1) s += __shfl_down_sync(0xffffffffu, s, d);
            if (lane == 0) lg[bb][oo] = s + b_out[oo];
        }
        __syncthreads();
        if (tid < 8) {
            float m = lg[tid][0];
#pragma unroll
            for (int i = 1; i < NOUT; ++i) m = fmaxf(m, lg[tid][i]);
            float sum = 0.f;
#pragma unroll
            for (int i = 0; i < NOUT; ++i) sum += __expf(lg[tid][i] - m);
            float lse = m + logf(sum);
#pragma unroll
            for (int i = 0; i < NOUT; ++i)
                out[(g + 8 * tid) * NOUT + i] = lg[tid][i] - lse;
        }
    }

    // keep cluster SMEM (mbarriers) alive until everyone is done
    asm volatile("barrier.cluster.arrive.aligned;" ::: "memory");
    asm volatile("barrier.cluster.wait.aligned;" ::: "memory");
}

// ---------------- launch ---------------------------------------------------
extern "C" void kernel_launch(void* const* d_in, const int* in_sizes, int n_in,
                              void* d_out, int out_size) {
    const int*   seq     = (const int*)d_in[0];
    const int*   lengths = (const int*)d_in[1];
    const float* emb     = (const float*)d_in[2];
    const float* w_ih    = (const float*)d_in[3];
    const float* w_hh    = (const float*)d_in[4];
    const float* b_ih    = (const float*)d_in[5];
    const float* b_hh    = (const float*)d_in[6];
    const float* w_out   = (const float*)d_in[7];
    const float* b_out   = (const float*)d_in[8];
    float*       out     = (float*)d_out;

    cudaFuncSetAttribute(k_xgates, cudaFuncAttributeMaxDynamicSharedMemorySize, P1_SMEM);
    cudaFuncSetAttribute(k_gru,    cudaFuncAttributeMaxDynamicSharedMemorySize, P2_SMEM);
    cudaFuncSetAttribute(k_gru,    cudaFuncAttributeNonPortableClusterSizeAllowed, 1);

    k_xgates<<<dim3(BATCH, SEQ / 64, G3 / 128), 256, P1_SMEM>>>(seq, lengths, emb, w_ih, b_ih);
    k_gru<<<dim3(16, 8), 384, P2_SMEM>>>(w_hh, b_hh, lengths, w_out, b_out, out);
}

// round 15
// speedup vs baseline: 1.4203x; 1.2503x over previous
#include <cuda_runtime.h>
#include <cstdint>

#define VOCAB 32000
#define EMB   256
#define HID   512
#define NOUT  5
#define SEQ   512
#define BATCH 64
#define G3    1536   // 3*HID

// ---------------- scratch (static device allocations only) ----------------
__device__ float g_xg[(size_t)SEQ * BATCH * G3];   // 201 MB: precomputed input gates
__device__ float g_h[2][BATCH * HID];              // double-buffered hidden state
__device__ float g_hfinal[BATCH * HID];            // final hidden per batch

struct alignas(128) PadInt { int v; int pad[31]; };
__device__ PadInt g_cnt[8];     // per-group arrival counter (own 128-B line)
__device__ PadInt g_epoch[8];   // per-group release epoch   (own 128-B line)

// ---------------- packed fp32x2 FMA (Blackwell; 2x FFMA throughput) -------
__device__ __forceinline__ void ffma2(unsigned long long& acc,
                                      unsigned long long a,
                                      unsigned long long b) {
    asm("fma.rn.f32x2 %0, %1, %2, %0;" : "+l"(acc) : "l"(a), "l"(b));
}
__device__ __forceinline__ float hsum2(unsigned long long v) {
    float lo = __uint_as_float((unsigned)(v & 0xffffffffull));
    float hi = __uint_as_float((unsigned)(v >> 32));
    return lo + hi;
}
__device__ __forceinline__ int ld_acq(const int* p) {
    int v; asm volatile("ld.global.acquire.gpu.b32 %0, [%1];" : "=r"(v) : "l"(p)); return v;
}
__device__ __forceinline__ void st_rel(int* p, int v) {
    asm volatile("st.global.release.gpu.b32 [%0], %1;" :: "l"(p), "r"(v));
}

// ---------------- phase 1: x_gates = emb[seq] @ w_ih^T + b_ih -------------
// grid (64 batch, 8 s-tiles of 64, 12 n-chunks of 128), 256 threads.
// Block (0,0,0) also resets the phase-2 barrier state (statics persist
// across graph replays; stream order makes this safe).
#define P1_SMEM ((64 * 260 + 128 * 258) * 4)
__global__ void __launch_bounds__(256, 1)
k_xgates(const int* __restrict__ seq, const int* __restrict__ lengths,
         const float* __restrict__ emb, const float* __restrict__ w_ih,
         const float* __restrict__ b_ih) {
    const int b = blockIdx.x, st = blockIdx.y, nc = blockIdx.z;
    const int s0 = st * 64, n0 = nc * 128;
    const int tid = threadIdx.x;

    if (b == 0 && st == 0 && nc == 0 && tid < 16) {
        if (tid < 8) g_cnt[tid].v = 0;
        else         g_epoch[tid - 8].v = 0;
    }
    if (s0 >= lengths[b]) return;  // dead steps never read downstream

    extern __shared__ float sm1[];
    float* xs = sm1;               // [64][260]
    float* ws = sm1 + 64 * 260;    // [128][258] = [kp][129 float2]

    {
        int r = tid >> 2, part = tid & 3;
        int tok = seq[(s0 + r) * BATCH + b];
        const float4* src = reinterpret_cast<const float4*>(emb) +
                            (size_t)tok * (EMB / 4) + part * 16;
        float* drow = xs + r * 260;
#pragma unroll
        for (int i = 0; i < 16; ++i) {
            float4 v = src[i];
            int k = (part * 16 + i) * 4;
            drow[k] = v.x; drow[k + 1] = v.y; drow[k + 2] = v.z; drow[k + 3] = v.w;
        }
    }
    {
        int n = tid >> 1, half = tid & 1;
        const float4* src = reinterpret_cast<const float4*>(
            w_ih + (size_t)(n0 + n) * EMB + half * 128);
#pragma unroll
        for (int i = 0; i < 32; ++i) {
            float4 v = src[i];
            int kp = half * 64 + i * 2;
            float* d0 = ws + (kp * 129 + n) * 2;
            d0[0] = v.x; d0[1] = v.y;
            float* d1 = ws + ((kp + 1) * 129 + n) * 2;
            d1[0] = v.z; d1[1] = v.w;
        }
    }
    __syncthreads();

    const int tn = tid & 15, ts = tid >> 4;
    unsigned long long acc[4][8];
#pragma unroll
    for (int i = 0; i < 4; ++i)
#pragma unroll
        for (int j = 0; j < 8; ++j) acc[i][j] = 0ull;

    const float* xbase = xs + ts * 260;
#pragma unroll 2
    for (int kp = 0; kp < 128; ++kp) {
        unsigned long long a[4], w[8];
#pragma unroll
        for (int i = 0; i < 4; ++i)
            a[i] = *reinterpret_cast<const unsigned long long*>(xbase + i * 16 * 260 + 2 * kp);
#pragma unroll
        for (int j = 0; j < 8; ++j)
            w[j] = *reinterpret_cast<const unsigned long long*>(ws + (kp * 129 + j * 16 + tn) * 2);
#pragma unroll
        for (int i = 0; i < 4; ++i)
#pragma unroll
            for (int j = 0; j < 8; ++j) ffma2(acc[i][j], a[i], w[j]);
    }
#pragma unroll
    for (int i = 0; i < 4; ++i) {
        int s = s0 + ts + i * 16;
        float* orow = g_xg + ((size_t)s * BATCH + b) * G3 + n0;
#pragma unroll
        for (int j = 0; j < 8; ++j) {
            int n = j * 16 + tn;
            orow[n] = hsum2(acc[i][j]) + b_ih[n0 + n];
        }
    }
}

// ---------------- phase 2: persistent GRU recurrence + fused output -------
// grid 148 (>=148 avoids the low-grid issue throttle); CTAs 128..147 exit.
// cid = 16*g + kg: 16 hidden-slices x 8 batch-groups. group g owns batches
// {g, g+8, ..., g+56} (lengths DESC in local bl). Weights persistent in
// SMEM [kp2][96 q] float4 (192 KB). GEMM thread = (kq8, qh): rows
// {qh, qh+48}, K-eighth. Only TWO GEMM variants (NB 8/4, unroll-4) to keep
// the hot loop inside the instruction cache; inactive slots read stale
// (finite) h and their results are discarded.
// Step sync: atomicAdd arrival + release-store epoch; every warp spins on
// ld.acquire (self-throttled by L2 latency, no nanosleep, no wake hop).
#define P2_SMEM ((128 * 96 * 4 + 8 * 512 + 4 * 8 * 96) * 4)

template <int NB>
__device__ __forceinline__ void gemm_q2(const ulonglong2* __restrict__ wp,
                                        const ulonglong2* __restrict__ hp,
                                        float* __restrict__ vA,
                                        float* __restrict__ vB) {
    unsigned long long aL[NB], aH[NB], bL[NB], bH[NB];
#pragma unroll
    for (int b = 0; b < NB; ++b) { aL[b] = 0; aH[b] = 0; bL[b] = 0; bH[b] = 0; }
#pragma unroll 4
    for (int i = 0; i < 16; ++i) {
        ulonglong2 wA = wp[i * 96];
        ulonglong2 wB = wp[i * 96 + 48];
#pragma unroll
        for (int b = 0; b < NB; ++b) {
            ulonglong2 h = hp[b * 128 + i];
            ffma2(aL[b], wA.x, h.x); ffma2(aH[b], wA.y, h.y);
            ffma2(bL[b], wB.x, h.x); ffma2(bH[b], wB.y, h.y);
        }
    }
#pragma unroll
    for (int b = 0; b < NB; ++b) {
        vA[b] = hsum2(aL[b]) + hsum2(aH[b]);
        vB[b] = hsum2(bL[b]) + hsum2(bH[b]);
    }
}

__global__ void __launch_bounds__(384, 1)
k_gru(const float* __restrict__ w_hh, const float* __restrict__ b_hh,
      const int* __restrict__ lengths, const float* __restrict__ w_out,
      const float* __restrict__ b_out, float* __restrict__ out) {
    const int cid = blockIdx.x;
    if (cid >= 128) return;            // pad CTAs (grid>=148) exit immediately
    const int kg = cid & 15;           // 0..15 hidden slice
    const int g  = cid >> 4;           // 0..7  batch group
    const int j0 = kg * 32;

    extern __shared__ float sm2[];
    float4* w4  = reinterpret_cast<float4*>(sm2);   // [128 kp2][96 q] 192KB
    float*  hsm = sm2 + 128 * 96 * 4;               // [8 bl][512]      16KB
    float*  hgp = hsm + 8 * 512;                    // [4 kqm][8 bl][96]12KB
    __shared__ int   len_loc[8];
    __shared__ float lg[8][NOUT];

    const int tid = threadIdx.x;
    const int kq8 = tid / 48;           // 0..7 K-eighth
    const int qh  = tid % 48;           // rows qh, qh+48
    const int kqm = kq8 & 3;
    const bool lo = (kq8 < 4);

    if (tid < 8) len_loc[tid] = lengths[g + 8 * tid];

    // persistent weight slice (once): w4[kp2*96+q] = w_hh[row(q)][4kp2..]
    for (int idx = tid; idx < 96 * 128; idx += 384) {
        int qq = idx >> 7, kp2 = idx & 127;
        int row = (qq / 32) * HID + j0 + (qq % 32);
        w4[kp2 * 96 + qq] =
            *(reinterpret_cast<const float4*>(w_hh + (size_t)row * HID) + kp2);
    }
    __syncthreads();

    const int nsteps = len_loc[0];      // lengths descending in bl

    // ---- pointwise thread state (tid < 256 handles one (bl, jl)) ----
    const bool pw = (tid < 256);
    const int bl = tid >> 5, jl = tid & 31;
    const int bg = g + 8 * bl;
    int mylen = 0;
    float bhr = 0.f, bhz = 0.f, bhn = 0.f;
    const float* xp = nullptr;
    size_t hoff = 0;
    float hcur = 0.f;
    if (pw) {
        mylen = len_loc[bl];
        bhr = b_hh[j0 + jl];
        bhz = b_hh[HID + j0 + jl];
        bhn = b_hh[2 * HID + j0 + jl];
        xp  = g_xg + (size_t)bg * G3 + j0 + jl;
        hoff = (size_t)bg * HID + j0 + jl;
    }

    const ulonglong2* wbase =
        reinterpret_cast<const ulonglong2*>(w4) + (size_t)(kq8 * 16) * 96 + qh;
    const ulonglong2* hbase =
        reinterpret_cast<const ulonglong2*>(hsm) + kq8 * 16;
    float* oA = hgp + kqm * 768 + qh;   // +b*96
    float* oB = oA + 48;
    int* ep = &g_epoch[g].v;

    for (int t = 0; t < nsteps; ++t) {
        float* hw = g_h[(t + 1) & 1];

        // prefetch this step's xg (DRAM) -- in flight through wait + GEMM
        float x0 = 0.f, x1 = 0.f, x2 = 0.f;
        const bool act = pw && (t < mylen);
        if (act) {
            x0 = __ldcs(xp);
            x1 = __ldcs(xp + HID);
            x2 = __ldcs(xp + 2 * HID);
            xp += (size_t)BATCH * G3;
        }

        if (t > 0) {
            // per-warp acquire spin: wakes independently, stages immediately.
            // (epoch >= t also guarantees own CTA finished its GEMM reads of
            //  hsm last step, so staging here is race-free.)
            while (ld_acq(ep) < t) {}

            const float* hr = g_h[t & 1];
            int A = 0;
#pragma unroll
            for (int i = 0; i < 8; ++i) A += (t < len_loc[i]) ? 1 : 0;

            // stage active h through L2
            for (int idx = tid; idx < A * 128; idx += 384) {
                int bb = idx >> 7, k4 = idx & 127;
                float4 v = __ldcg(
                    reinterpret_cast<const float4*>(hr) + (size_t)(g + 8 * bb) * 128 + k4);
                reinterpret_cast<float4*>(hsm)[bb * 128 + k4] = v;
            }
            __syncthreads();

            // GEMM (uniform branch: A identical across CTA)
            if (A > 4) {
                float vA[8], vB[8];
                gemm_q2<8>(wbase, hbase, vA, vB);
                if (lo) {
#pragma unroll
                    for (int b = 0; b < 8; ++b) { oA[b * 96] = vA[b]; oB[b * 96] = vB[b]; }
                }
                __syncthreads();
                if (!lo) {
#pragma unroll
                    for (int b = 0; b < 8; ++b) { oA[b * 96] += vA[b]; oB[b * 96] += vB[b]; }
                }
            } else {
                float vA[4], vB[4];
                gemm_q2<4>(wbase, hbase, vA, vB);
                if (lo) {
#pragma unroll
                    for (int b = 0; b < 4; ++b) { oA[b * 96] = vA[b]; oB[b * 96] = vB[b]; }
                }
                __syncthreads();
                if (!lo) {
#pragma unroll
                    for (int b = 0; b < 4; ++b) { oA[b * 96] += vA[b]; oB[b * 96] += vB[b]; }
                }
            }
            __syncthreads();
        }

        // ---- pointwise GRU update (h element lives in hcur register) ----
        if (act) {
            float sr = 0.f, sz = 0.f, sn = 0.f;
            if (t > 0) {
                const float* hgb = hgp + bl * 96 + jl;
                sr = hgb[0]  + hgb[768]      + hgb[1536]      + hgb[2304];
                sz = hgb[32] + hgb[768 + 32] + hgb[1536 + 32] + hgb[2304 + 32];
                sn = hgb[64] + hgb[768 + 64] + hgb[1536 + 64] + hgb[2304 + 64];
            }
            float gr  = sr + bhr + x0;
            float gz  = sz + bhz + x1;
            float gnh = sn + bhn;
            float r = 1.0f / (1.0f + __expf(-gr));
            float z = 1.0f / (1.0f + __expf(-gz));
            float n = tanhf(x2 + r * gnh);
            hcur = (1.0f - z) * n + z * hcur;
            hw[hoff] = hcur;
            __threadfence();            // publish h before the arrival below
        }

        // ---- arrival: relaxed add; last arriver releases the epoch ----
        __syncthreads();                // all pw stores + fences done CTA-wide
        if (tid == 0) {
            int arr = atomicAdd(&g_cnt[g].v, 1) + 1;
            if (arr == 16 * (t + 1)) st_rel(ep, t + 1);
        }
        // no trailing sync: next iteration's epoch wait subsumes it
    }

    // ---- final round: publish h, arrive, rank kg==0 computes the head ----
    if (pw) {
        g_hfinal[hoff] = hcur;
        __threadfence();
    }
    __syncthreads();
    if (tid == 0) {
        int arr = atomicAdd(&g_cnt[g].v, 1) + 1;
        if (arr == 16 * (nsteps + 1)) st_rel(ep, nsteps + 1);
    }

    if (kg == 0) {
        while (ld_acq(ep) < nsteps + 1) {}
        const int wid = tid >> 5, lane = tid & 31;
        for (int p = wid; p < 8 * NOUT; p += 12) {
            int bb = p / NOUT, oo = p % NOUT;
            const float4* h4 =
                reinterpret_cast<const float4*>(g_hfinal + (size_t)(g + 8 * bb) * HID);
            const float4* w4o =
                reinterpret_cast<const float4*>(w_out + (size_t)oo * HID);
            float s = 0.f;
#pragma unroll
            for (int i = 0; i < 4; ++i) {
                float4 hv = __ldcg(h4 + lane + 32 * i);
                float4 wv = w4o[lane + 32 * i];
                s += hv.x * wv.x + hv.y * wv.y + hv.z * wv.z + hv.w * wv.w;
            }
#pragma unroll
            for (int d = 16; d; d >>= 1) s += __shfl_down_sync(0xffffffffu, s, d);
            if (lane == 0) lg[bb][oo] = s + b_out[oo];
        }
        __syncthreads();
        if (tid < 8) {
            float m = lg[tid][0];
#pragma unroll
            for (int i = 1; i < NOUT; ++i) m = fmaxf(m, lg[tid][i]);
            float sum = 0.f;
#pragma unroll
            for (int i = 0; i < NOUT; ++i) sum += __expf(lg[tid][i] - m);
            float lse = m + logf(sum);
#pragma unroll
            for (int i = 0; i < NOUT; ++i)
                out[(g + 8 * tid) * NOUT + i] = lg[tid][i] - lse;
        }
    }
}

// ---------------- launch ---------------------------------------------------
extern "C" void kernel_launch(void* const* d_in, const int* in_sizes, int n_in,
                              void* d_out, int out_size) {
    const int*   seq     = (const int*)d_in[0];
    const int*   lengths = (const int*)d_in[1];
    const float* emb     = (const float*)d_in[2];
    const float* w_ih    = (const float*)d_in[3];
    const float* w_hh    = (const float*)d_in[4];
    const float* b_ih    = (const float*)d_in[5];
    const float* b_hh    = (const float*)d_in[6];
    const float* w_out   = (const float*)d_in[7];
    const float* b_out   = (const float*)d_in[8];
    float*       out     = (float*)d_out;

    cudaFuncSetAttribute(k_xgates, cudaFuncAttributeMaxDynamicSharedMemorySize, P1_SMEM);
    cudaFuncSetAttribute(k_gru,    cudaFuncAttributeMaxDynamicSharedMemorySize, P2_SMEM);

    k_xgates<<<dim3(BATCH, SEQ / 64, G3 / 128), 256, P1_SMEM>>>(seq, lengths, emb, w_ih, b_ih);
    k_gru<<<148, 384, P2_SMEM>>>(w_hh, b_hh, lengths, w_out, b_out, out);
}